// round 3
// baseline (speedup 1.0000x reference)
#include <cuda_runtime.h>
#include <math.h>

#define BATCH  4
#define LEN    2048
#define DMODEL 1024
#define DIN    2048
#define DSTATE 16
#define DTRANK 64
#define DCONV  4
#define ML     (BATCH * LEN)          // 8192 rows
#define DBCW   (DTRANK + 2 * DSTATE)  // 96

// ---------------- scratch (static device globals; no allocations) ----------
__device__ float g_xz[(size_t)ML * 2 * DIN];   // in-proj output (xc | z), 134 MB
__device__ float g_xc[(size_t)ML * DIN];       // conv+silu output
__device__ float g_dbc[(size_t)ML * DBCW];     // dt | B | C
__device__ float g_delta[(size_t)ML * DIN];    // softplus(dt @ W_dt + b)
__device__ float g_y[(size_t)ML * DIN];        // scan output * silu(z)

// ---------------- generic NT SGEMM: C[m,n] = sum_k A[m,k] * B[n,k] --------
// BM=BN=128, BK=8, 256 threads, 8x8 per thread. M must be /128, K /8.
// N guarded (for the 96-wide x-proj).
__global__ __launch_bounds__(256) void sgemm_nt(
    const float* __restrict__ A, const float* __restrict__ B,
    float* __restrict__ C, int M, int N, int K)
{
    __shared__ float As[8][128];
    __shared__ float Bs[8][128];

    const int tid = threadIdx.x;
    const int m0 = blockIdx.y * 128;
    const int n0 = blockIdx.x * 128;

    const int lr = tid >> 1;          // 0..127: row within tile
    const int lk = (tid & 1) * 4;     // 0 or 4: k offset

    const float* Ag = A + (size_t)(m0 + lr) * K + lk;
    const bool bvalid = (n0 + lr) < N;
    const float* Bg = B + (size_t)(bvalid ? (n0 + lr) : 0) * K + lk;

    const int tx = tid & 15;          // n-group
    const int ty = tid >> 4;          // m-group

    float acc[8][8];
#pragma unroll
    for (int i = 0; i < 8; i++)
#pragma unroll
        for (int j = 0; j < 8; j++) acc[i][j] = 0.f;

    for (int k0 = 0; k0 < K; k0 += 8) {
        float4 av = *(const float4*)(Ag + k0);
        float4 bv = bvalid ? *(const float4*)(Bg + k0) : make_float4(0.f, 0.f, 0.f, 0.f);
        __syncthreads();
        As[lk + 0][lr] = av.x; As[lk + 1][lr] = av.y;
        As[lk + 2][lr] = av.z; As[lk + 3][lr] = av.w;
        Bs[lk + 0][lr] = bv.x; Bs[lk + 1][lr] = bv.y;
        Bs[lk + 2][lr] = bv.z; Bs[lk + 3][lr] = bv.w;
        __syncthreads();
#pragma unroll
        for (int kk = 0; kk < 8; kk++) {
            float4 a0 = *(const float4*)&As[kk][ty * 8];
            float4 a1 = *(const float4*)&As[kk][ty * 8 + 4];
            float4 b0 = *(const float4*)&Bs[kk][tx * 8];
            float4 b1 = *(const float4*)&Bs[kk][tx * 8 + 4];
            float a[8] = {a0.x, a0.y, a0.z, a0.w, a1.x, a1.y, a1.z, a1.w};
            float b[8] = {b0.x, b0.y, b0.z, b0.w, b1.x, b1.y, b1.z, b1.w};
#pragma unroll
            for (int i = 0; i < 8; i++)
#pragma unroll
                for (int j = 0; j < 8; j++) acc[i][j] = fmaf(a[i], b[j], acc[i][j]);
        }
    }

#pragma unroll
    for (int i = 0; i < 8; i++) {
        int m = m0 + ty * 8 + i;
#pragma unroll
        for (int j = 0; j < 8; j++) {
            int n = n0 + tx * 8 + j;
            if (n < N) C[(size_t)m * N + n] = acc[i][j];
        }
    }
}

// ---------------- causal depthwise conv (k=4) + bias + SiLU ----------------
__global__ __launch_bounds__(256) void conv_silu_kernel(
    const float* __restrict__ w, const float* __restrict__ bias)
{
    int idx = blockIdx.x * blockDim.x + threadIdx.x;
    if (idx >= ML * DIN) return;
    int d = idx & (DIN - 1);
    int l = (idx >> 11) & (LEN - 1);
    int b = idx >> 22;

    float acc = bias[d];
    const float* wd = w + d * DCONV;
#pragma unroll
    for (int j = 0; j < DCONV; j++) {
        int ll = l - (DCONV - 1) + j;
        if (ll >= 0)
            acc = fmaf(wd[j], g_xz[((size_t)(b * LEN + ll)) * (2 * DIN) + d], acc);
    }
    // SiLU
    float s = acc / (1.f + expf(-acc));
    g_xc[idx] = s;
}

// ---------------- delta = softplus(dt @ W_dt^T + b_dt) --------------------
// block: 16 rows, 256 threads; grid.x = ML/16
__global__ __launch_bounds__(256) void delta_kernel(
    const float* __restrict__ W_dt, const float* __restrict__ b_dt)
{
    __shared__ float dts[16][DTRANK];
    const int tid = threadIdx.x;
    const int m0 = blockIdx.x * 16;

    // load 16x64 dt block (first 64 cols of dbc rows)
    {
        int flat = tid * 4;
        int r = flat >> 6, c = flat & 63;
        float4 v = *(const float4*)&g_dbc[(size_t)(m0 + r) * DBCW + c];
        dts[r][c] = v.x; dts[r][c + 1] = v.y; dts[r][c + 2] = v.z; dts[r][c + 3] = v.w;
    }
    __syncthreads();

    for (int d = tid; d < DIN; d += 256) {
        float bd = b_dt[d];
        float acc[16];
#pragma unroll
        for (int m = 0; m < 16; m++) acc[m] = bd;
        const float* wrow = W_dt + (size_t)d * DTRANK;
#pragma unroll 4
        for (int k4 = 0; k4 < DTRANK / 4; k4++) {
            float4 wv = *(const float4*)(wrow + k4 * 4);
#pragma unroll
            for (int m = 0; m < 16; m++) {
                acc[m] = fmaf(dts[m][k4 * 4 + 0], wv.x, acc[m]);
                acc[m] = fmaf(dts[m][k4 * 4 + 1], wv.y, acc[m]);
                acc[m] = fmaf(dts[m][k4 * 4 + 2], wv.z, acc[m]);
                acc[m] = fmaf(dts[m][k4 * 4 + 3], wv.w, acc[m]);
            }
        }
#pragma unroll
        for (int m = 0; m < 16; m++) {
            float x = acc[m];
            // stable softplus: max(x,0) + log1p(exp(-|x|))
            float sp = fmaxf(x, 0.f) + log1pf(expf(-fabsf(x)));
            g_delta[(size_t)(m0 + m) * DIN + d] = sp;
        }
    }
}

// ---------------- selective scan + D skip + SiLU(z) gate -------------------
// grid: (DIN/128, BATCH), 128 threads; one channel per thread, 16 states in regs
__global__ __launch_bounds__(128) void scan_kernel(
    const float* __restrict__ A_raw, const float* __restrict__ Dp)
{
    const int b = blockIdx.y;
    const int d = blockIdx.x * 128 + threadIdx.x;

    float A2[DSTATE];
#pragma unroll
    for (int n = 0; n < DSTATE; n++)
        A2[n] = -expf(A_raw[(size_t)n * DIN + d]) * 1.4426950408889634f; // * log2(e)
    const float Dd = Dp[d];

    float h[DSTATE];
#pragma unroll
    for (int n = 0; n < DSTATE; n++) h[n] = 0.f;

    __shared__ float BC[2 * DSTATE];
    const float* dbc_b = g_dbc + (size_t)b * LEN * DBCW;
    const size_t row0 = (size_t)b * LEN;

    for (int l = 0; l < LEN; l++) {
        if (threadIdx.x < 2 * DSTATE)
            BC[threadIdx.x] = dbc_b[(size_t)l * DBCW + DTRANK + threadIdx.x];
        __syncthreads();

        size_t ridx = (row0 + l) * DIN + d;
        float dlt = g_delta[ridx];
        float xv  = g_xc[ridx];
        float zv  = g_xz[(row0 + l) * (2 * DIN) + DIN + d];

        float dx = dlt * xv;
        float yv = 0.f;
#pragma unroll
        for (int n = 0; n < DSTATE; n++) {
            float dA = exp2f(dlt * A2[n]);
            h[n] = fmaf(dA, h[n], BC[n] * dx);
            yv = fmaf(BC[DSTATE + n], h[n], yv);
        }
        yv = fmaf(Dd, xv, yv);
        float gate = zv / (1.f + expf(-zv));
        g_y[ridx] = yv * gate;
        __syncthreads();
    }
}

// ---------------- launch ---------------------------------------------------
extern "C" void kernel_launch(void* const* d_in, const int* in_sizes, int n_in,
                              void* d_out, int out_size)
{
    const float* x      = (const float*)d_in[0];  // (4,2048,1024)
    const float* W_in   = (const float*)d_in[1];  // (4096,1024)
    const float* conv_w = (const float*)d_in[2];  // (2048,1,4)
    const float* conv_b = (const float*)d_in[3];  // (2048,)
    const float* W_x    = (const float*)d_in[4];  // (96,2048)
    const float* W_dt   = (const float*)d_in[5];  // (2048,64)
    const float* b_dt   = (const float*)d_in[6];  // (2048,)
    const float* A_raw  = (const float*)d_in[7];  // (16,2048)
    const float* Dp     = (const float*)d_in[8];  // (2048,)
    const float* W_out  = (const float*)d_in[9];  // (1024,2048)
    float* out = (float*)d_out;                   // (4,2048,1024)

    float *p_xz, *p_xc, *p_dbc, *p_y;
    cudaGetSymbolAddress((void**)&p_xz,  g_xz);
    cudaGetSymbolAddress((void**)&p_xc,  g_xc);
    cudaGetSymbolAddress((void**)&p_dbc, g_dbc);
    cudaGetSymbolAddress((void**)&p_y,   g_y);

    // 1. in-proj: xz = x @ W_in^T   (M=8192, N=4096, K=1024)
    {
        dim3 grid(2 * DIN / 128, ML / 128);
        sgemm_nt<<<grid, 256>>>(x, W_in, p_xz, ML, 2 * DIN, DMODEL);
    }
    // 2. causal conv + SiLU
    {
        int total = ML * DIN;
        conv_silu_kernel<<<(total + 255) / 256, 256>>>(conv_w, conv_b);
    }
    // 3. x-proj: dbc = xc @ W_x^T   (M=8192, N=96, K=2048)
    {
        dim3 grid(1, ML / 128);
        sgemm_nt<<<grid, 256>>>(p_xc, W_x, p_dbc, ML, DBCW, DIN);
    }
    // 4. delta
    delta_kernel<<<ML / 16, 256>>>(W_dt, b_dt);
    // 5. selective scan (+gate)
    {
        dim3 grid(DIN / 128, BATCH);
        scan_kernel<<<grid, 128>>>(A_raw, Dp);
    }
    // 6. out-proj: out = y @ W_out^T (M=8192, N=1024, K=2048)
    {
        dim3 grid(DMODEL / 128, ML / 128);
        sgemm_nt<<<grid, 256>>>(p_y, W_out, out, ML, DMODEL, DIN);
    }
}

// round 6
// speedup vs baseline: 1.8173x; 1.8173x over previous
#include <cuda_runtime.h>
#include <cuda_bf16.h>
#include <math.h>
#include <stdint.h>

#define BATCH  4
#define LEN    2048
#define DMODEL 1024
#define DIN    2048
#define DSTATE 16
#define DTRANK 64
#define DCONV  4
#define ML     (BATCH * LEN)          // 8192 rows
#define DBCW   (DTRANK + 2 * DSTATE)  // 96

// ---------------- fp32 scratch ----------------
__device__ float g_xz[(size_t)ML * 2 * DIN];   // in-proj output (xc | z)
__device__ float g_xc[(size_t)ML * DIN];       // conv+silu output (fp32 for scan)
__device__ float g_dbc[(size_t)ML * DBCW];     // dt | B | C
__device__ float g_delta[(size_t)ML * DIN];    // softplus(dt @ W_dt + b)

// ---------------- bf16 hi/lo scratch ----------------
__device__ __align__(16) __nv_bfloat16 g_xh[(size_t)ML * DMODEL];
__device__ __align__(16) __nv_bfloat16 g_xl[(size_t)ML * DMODEL];
__device__ __align__(16) __nv_bfloat16 g_Winh[(size_t)2 * DIN * DMODEL];
__device__ __align__(16) __nv_bfloat16 g_Winl[(size_t)2 * DIN * DMODEL];
__device__ __align__(16) __nv_bfloat16 g_xch[(size_t)ML * DIN];
__device__ __align__(16) __nv_bfloat16 g_xcl[(size_t)ML * DIN];
__device__ __align__(16) __nv_bfloat16 g_Wxh[(size_t)DBCW * DIN];
__device__ __align__(16) __nv_bfloat16 g_Wxl[(size_t)DBCW * DIN];
__device__ __align__(16) __nv_bfloat16 g_dth[(size_t)ML * DTRANK];
__device__ __align__(16) __nv_bfloat16 g_dtl[(size_t)ML * DTRANK];
__device__ __align__(16) __nv_bfloat16 g_Wdth[(size_t)DIN * DTRANK];
__device__ __align__(16) __nv_bfloat16 g_Wdtl[(size_t)DIN * DTRANK];
__device__ __align__(16) __nv_bfloat16 g_yh[(size_t)ML * DIN];
__device__ __align__(16) __nv_bfloat16 g_yl[(size_t)ML * DIN];
__device__ __align__(16) __nv_bfloat16 g_Wouth[(size_t)DMODEL * DIN];
__device__ __align__(16) __nv_bfloat16 g_Woutl[(size_t)DMODEL * DIN];

// ---------------- PTX helpers (base sm_103-legal only) ----------------
__device__ __forceinline__ uint32_t s2u(const void* p) {
    uint32_t a;
    asm("{ .reg .u64 t; cvta.to.shared.u64 t, %1; cvt.u32.u64 %0, t; }" : "=r"(a) : "l"(p));
    return a;
}
__device__ __forceinline__ void cpasync16(uint32_t dst, const void* src, int sz) {
    asm volatile("cp.async.cg.shared.global [%0], [%1], 16, %2;"
                 :: "r"(dst), "l"(src), "r"(sz) : "memory");
}
__device__ __forceinline__ void ldsm4(uint32_t* r, uint32_t addr) {
    asm volatile("ldmatrix.sync.aligned.m8n8.x4.shared.b16 {%0,%1,%2,%3}, [%4];"
                 : "=r"(r[0]), "=r"(r[1]), "=r"(r[2]), "=r"(r[3]) : "r"(addr));
}
__device__ __forceinline__ void mma16816(float* d, const uint32_t* a,
                                         uint32_t b0, uint32_t b1) {
    asm volatile(
        "mma.sync.aligned.m16n8k16.row.col.f32.bf16.bf16.f32 "
        "{%0,%1,%2,%3}, {%4,%5,%6,%7}, {%8,%9}, {%0,%1,%2,%3};"
        : "+f"(d[0]), "+f"(d[1]), "+f"(d[2]), "+f"(d[3])
        : "r"(a[0]), "r"(a[1]), "r"(a[2]), "r"(a[3]), "r"(b0), "r"(b1));
}
#define SWZ(o) ((o) ^ (((o) >> 3) & 0x70))

// ============================================================================
// split-bf16 GEMM (mma.sync):  C[m,n] = sum_k A[m,k]*B[n,k]
//   3 K-segments: Ah*Bh + Al*Bh + Ah*Bl.  CTA tile 128x128, BK=64,
//   double-buffered cp.async, SW128 swizzle, 8 warps @ 64x32.
//   M % 128 == 0, K % 64 == 0, N % 32 == 0 (B rows >= N zero-filled).
//   EPI: 0 = plain store, 1 = softplus(acc + bias[n]).
// ============================================================================
template <int EPI>
__global__ __launch_bounds__(256) void gemm_hl(
    const __nv_bfloat16* __restrict__ Ah, const __nv_bfloat16* __restrict__ Al,
    const __nv_bfloat16* __restrict__ Bh, const __nv_bfloat16* __restrict__ Bl,
    float* __restrict__ C, int N, int K, const float* __restrict__ bias)
{
    extern __shared__ char dsm[];
    char* base = (char*)((((uintptr_t)dsm) + 1023) & ~(uintptr_t)1023);
    const uint32_t sA[2] = { s2u(base),         s2u(base) + 16384 };
    const uint32_t sB[2] = { s2u(base) + 32768, s2u(base) + 49152 };

    const int tid = threadIdx.x, lane = tid & 31, wid = tid >> 5;
    const int wm = (wid >> 2) * 64, wn = (wid & 3) * 32;
    const int m0 = blockIdx.y * 128, n0 = blockIdx.x * 128;
    const int kcs = K >> 6, T = 3 * kcs;

    float acc[4][4][4];
#pragma unroll
    for (int i = 0; i < 4; i++)
#pragma unroll
        for (int j = 0; j < 4; j++)
#pragma unroll
            for (int r = 0; r < 4; r++) acc[i][j][r] = 0.f;

    // chunk loader: 128x64 bf16 tiles for A and B, swizzled
    auto loadChunk = [&](int c, int buf) {
        const int seg = c / kcs, kc = c - seg * kcs, koff = kc * 64;
        const __nv_bfloat16* Ap = (seg == 1) ? Al : Ah;
        const __nv_bfloat16* Bp = (seg == 2) ? Bl : Bh;
#pragma unroll
        for (int q = 0; q < 4; q++) {
            int idx = tid + q * 256, r = idx >> 3, c8 = idx & 7;
            uint32_t o = (uint32_t)(r * 128 + c8 * 16);
            cpasync16(sA[buf] + SWZ(o), Ap + (size_t)(m0 + r) * K + koff + c8 * 8, 16);
        }
#pragma unroll
        for (int q = 0; q < 4; q++) {
            int idx = tid + q * 256, r = idx >> 3, c8 = idx & 7;
            int nr = n0 + r;
            int ok = (nr < N) ? 16 : 0;
            uint32_t o = (uint32_t)(r * 128 + c8 * 16);
            cpasync16(sB[buf] + SWZ(o),
                      Bp + (size_t)((nr < N) ? nr : 0) * K + koff + c8 * 8, ok);
        }
        asm volatile("cp.async.commit_group;" ::: "memory");
    };

    loadChunk(0, 0);
    for (int c = 0; c < T; c++) {
        const int buf = c & 1;
        if (c + 1 < T) {
            loadChunk(c + 1, buf ^ 1);
            asm volatile("cp.async.wait_group 1;" ::: "memory");
        } else {
            asm volatile("cp.async.wait_group 0;" ::: "memory");
        }
        __syncthreads();

#pragma unroll
        for (int kb = 0; kb < 64; kb += 16) {
            uint32_t af[4][4], bfr[2][4];
            const int rsel = lane & 15;
            const int kk = kb + ((lane & 16) >> 1);   // +8 for upper half-warp
#pragma unroll
            for (int mi = 0; mi < 4; mi++) {
                uint32_t o = (uint32_t)((wm + mi * 16 + rsel) * 128 + kk * 2);
                ldsm4(af[mi], sA[buf] + SWZ(o));
            }
#pragma unroll
            for (int nb = 0; nb < 2; nb++) {
                uint32_t o = (uint32_t)((wn + nb * 16 + rsel) * 128 + kk * 2);
                ldsm4(bfr[nb], sB[buf] + SWZ(o));
            }
#pragma unroll
            for (int mi = 0; mi < 4; mi++)
#pragma unroll
                for (int nj = 0; nj < 4; nj++)
                    mma16816(acc[mi][nj], af[mi],
                             bfr[nj >> 1][nj & 1], bfr[nj >> 1][(nj & 1) + 2]);
        }
        __syncthreads();
    }

    // epilogue
#pragma unroll
    for (int mi = 0; mi < 4; mi++)
#pragma unroll
        for (int h = 0; h < 2; h++) {
            int m = m0 + wm + mi * 16 + (lane >> 2) + h * 8;
#pragma unroll
            for (int nj = 0; nj < 4; nj++) {
                int n = n0 + wn + nj * 8 + (lane & 3) * 2;
                if (n < N) {
                    float v0 = acc[mi][nj][h * 2 + 0];
                    float v1 = acc[mi][nj][h * 2 + 1];
                    if (EPI == 1) {
                        v0 += bias[n];
                        v1 += bias[n + 1];
                        v0 = fmaxf(v0, 0.f) + log1pf(expf(-fabsf(v0)));
                        v1 = fmaxf(v1, 0.f) + log1pf(expf(-fabsf(v1)));
                    }
                    float2 f2 = make_float2(v0, v1);
                    *(float2*)(C + (size_t)m * N + n) = f2;
                }
            }
        }
}

// ---------------- fp32 -> (hi, lo) bf16 split, contiguous ----------------
__global__ __launch_bounds__(256) void split_hl(
    const float* __restrict__ src, __nv_bfloat16* __restrict__ h,
    __nv_bfloat16* __restrict__ l, int n4)
{
    int i = blockIdx.x * 256 + threadIdx.x;
    if (i >= n4) return;
    float4 v = ((const float4*)src)[i];
    __nv_bfloat16 h0 = __float2bfloat16(v.x), h1 = __float2bfloat16(v.y);
    __nv_bfloat16 h2 = __float2bfloat16(v.z), h3 = __float2bfloat16(v.w);
    __nv_bfloat16 l0 = __float2bfloat16(v.x - __bfloat162float(h0));
    __nv_bfloat16 l1 = __float2bfloat16(v.y - __bfloat162float(h1));
    __nv_bfloat16 l2 = __float2bfloat16(v.z - __bfloat162float(h2));
    __nv_bfloat16 l3 = __float2bfloat16(v.w - __bfloat162float(h3));
    ((__nv_bfloat162*)h)[i * 2 + 0] = __nv_bfloat162(h0, h1);
    ((__nv_bfloat162*)h)[i * 2 + 1] = __nv_bfloat162(h2, h3);
    ((__nv_bfloat162*)l)[i * 2 + 0] = __nv_bfloat162(l0, l1);
    ((__nv_bfloat162*)l)[i * 2 + 1] = __nv_bfloat162(l2, l3);
}

// ---------------- dt slice (cols 0..63 of g_dbc) -> hi/lo ----------------
__global__ __launch_bounds__(256) void split_dt_kernel()
{
    int i = blockIdx.x * 256 + threadIdx.x;          // over ML*16, 4 elems each
    if (i >= ML * 16) return;
    int r = i >> 4, c = (i & 15) * 4;
    float4 v = *(const float4*)&g_dbc[(size_t)r * DBCW + c];
    __nv_bfloat16 h0 = __float2bfloat16(v.x), h1 = __float2bfloat16(v.y);
    __nv_bfloat16 h2 = __float2bfloat16(v.z), h3 = __float2bfloat16(v.w);
    __nv_bfloat16 l0 = __float2bfloat16(v.x - __bfloat162float(h0));
    __nv_bfloat16 l1 = __float2bfloat16(v.y - __bfloat162float(h1));
    __nv_bfloat16 l2 = __float2bfloat16(v.z - __bfloat162float(h2));
    __nv_bfloat16 l3 = __float2bfloat16(v.w - __bfloat162float(h3));
    size_t o = (size_t)r * DTRANK + c;
    ((__nv_bfloat162*)(g_dth + o))[0] = __nv_bfloat162(h0, h1);
    ((__nv_bfloat162*)(g_dth + o))[1] = __nv_bfloat162(h2, h3);
    ((__nv_bfloat162*)(g_dtl + o))[0] = __nv_bfloat162(l0, l1);
    ((__nv_bfloat162*)(g_dtl + o))[1] = __nv_bfloat162(l2, l3);
}

// ---------------- causal depthwise conv (k=4) + bias + SiLU + bf16 split ----
__global__ __launch_bounds__(256) void conv_silu_kernel(
    const float* __restrict__ w, const float* __restrict__ bias)
{
    int idx = blockIdx.x * blockDim.x + threadIdx.x;
    if (idx >= ML * DIN) return;
    int d = idx & (DIN - 1);
    int l = (idx >> 11) & (LEN - 1);
    int b = idx >> 22;

    float acc = bias[d];
    const float* wd = w + d * DCONV;
#pragma unroll
    for (int j = 0; j < DCONV; j++) {
        int ll = l - (DCONV - 1) + j;
        if (ll >= 0)
            acc = fmaf(wd[j], g_xz[((size_t)(b * LEN + ll)) * (2 * DIN) + d], acc);
    }
    float s = acc / (1.f + __expf(-acc));
    g_xc[idx] = s;
    __nv_bfloat16 hi = __float2bfloat16(s);
    g_xch[idx] = hi;
    g_xcl[idx] = __float2bfloat16(s - __bfloat162float(hi));
}

// ---------------- selective scan + D skip + SiLU(z) gate + bf16 split ------
// grid (DIN/64, BATCH), 256 threads: 64 channels x 4 state-quads.
__global__ __launch_bounds__(256) void scan_kernel(
    const float* __restrict__ A_raw, const float* __restrict__ Dp)
{
    const int b = blockIdx.y;
    const int d = blockIdx.x * 64 + (threadIdx.x >> 2);
    const int q = threadIdx.x & 3;
    const int n0 = q * 4;

    float A2[4];
#pragma unroll
    for (int n = 0; n < 4; n++)
        A2[n] = -expf(A_raw[(size_t)(n0 + n) * DIN + d]) * 1.4426950408889634f;
    const float Dd = Dp[d];

    float h[4] = {0.f, 0.f, 0.f, 0.f};
    const float* dbcb = g_dbc + (size_t)b * LEN * DBCW + DTRANK;
    const size_t base = (size_t)b * LEN;

    // prefetch l = 0
    size_t r0 = base * DIN + d;
    float dlt = g_delta[r0];
    float xv  = g_xc[r0];
    float zv  = g_xz[base * (2 * DIN) + DIN + d];

    for (int l = 0; l < LEN; l++) {
        float c_dlt = dlt, c_x = xv, c_z = zv;
        int ln = (l + 1 < LEN) ? l + 1 : l;            // prefetch next
        size_t rn = (base + ln) * DIN + d;
        dlt = g_delta[rn];
        xv  = g_xc[rn];
        zv  = g_xz[(base + ln) * (2 * DIN) + DIN + d];

        const float* bc = dbcb + (size_t)l * DBCW;
        float dx = c_dlt * c_x;
        float yv = 0.f;
#pragma unroll
        for (int n = 0; n < 4; n++) {
            float Bn = bc[n0 + n];
            float Cn = bc[DSTATE + n0 + n];
            float dA = exp2f(c_dlt * A2[n]);
            h[n] = fmaf(dA, h[n], Bn * dx);
            yv = fmaf(Cn, h[n], yv);
        }
        yv += __shfl_xor_sync(0xFFFFFFFFu, yv, 1);
        yv += __shfl_xor_sync(0xFFFFFFFFu, yv, 2);
        if (q == 0) {
            float y = fmaf(Dd, c_x, yv);
            float gate = c_z / (1.f + __expf(-c_z));
            float o = y * gate;
            size_t oi = (base + l) * DIN + d;
            __nv_bfloat16 hi = __float2bfloat16(o);
            g_yh[oi] = hi;
            g_yl[oi] = __float2bfloat16(o - __bfloat162float(hi));
        }
    }
}

// ---------------- launch ---------------------------------------------------
extern "C" void kernel_launch(void* const* d_in, const int* in_sizes, int n_in,
                              void* d_out, int out_size)
{
    const float* x      = (const float*)d_in[0];
    const float* W_in   = (const float*)d_in[1];
    const float* conv_w = (const float*)d_in[2];
    const float* conv_b = (const float*)d_in[3];
    const float* W_x    = (const float*)d_in[4];
    const float* W_dt   = (const float*)d_in[5];
    const float* b_dt   = (const float*)d_in[6];
    const float* A_raw  = (const float*)d_in[7];
    const float* Dp     = (const float*)d_in[8];
    const float* W_out  = (const float*)d_in[9];
    float* out = (float*)d_out;

    float *p_xz, *p_dbc, *p_delta;
    __nv_bfloat16 *p_xh, *p_xl, *p_Winh, *p_Winl, *p_xch, *p_xcl, *p_Wxh, *p_Wxl;
    __nv_bfloat16 *p_dth, *p_dtl, *p_Wdth, *p_Wdtl, *p_yh, *p_yl, *p_Wouth, *p_Woutl;
    cudaGetSymbolAddress((void**)&p_xz,    g_xz);
    cudaGetSymbolAddress((void**)&p_dbc,   g_dbc);
    cudaGetSymbolAddress((void**)&p_delta, g_delta);
    cudaGetSymbolAddress((void**)&p_xh,    g_xh);
    cudaGetSymbolAddress((void**)&p_xl,    g_xl);
    cudaGetSymbolAddress((void**)&p_Winh,  g_Winh);
    cudaGetSymbolAddress((void**)&p_Winl,  g_Winl);
    cudaGetSymbolAddress((void**)&p_xch,   g_xch);
    cudaGetSymbolAddress((void**)&p_xcl,   g_xcl);
    cudaGetSymbolAddress((void**)&p_Wxh,   g_Wxh);
    cudaGetSymbolAddress((void**)&p_Wxl,   g_Wxl);
    cudaGetSymbolAddress((void**)&p_dth,   g_dth);
    cudaGetSymbolAddress((void**)&p_dtl,   g_dtl);
    cudaGetSymbolAddress((void**)&p_Wdth,  g_Wdth);
    cudaGetSymbolAddress((void**)&p_Wdtl,  g_Wdtl);
    cudaGetSymbolAddress((void**)&p_yh,    g_yh);
    cudaGetSymbolAddress((void**)&p_yl,    g_yl);
    cudaGetSymbolAddress((void**)&p_Wouth, g_Wouth);
    cudaGetSymbolAddress((void**)&p_Woutl, g_Woutl);

    const int GSMEM = 1024 + 4 * 16384;   // align slack + 4 tiles
    cudaFuncSetAttribute(gemm_hl<0>, cudaFuncAttributeMaxDynamicSharedMemorySize, GSMEM);
    cudaFuncSetAttribute(gemm_hl<1>, cudaFuncAttributeMaxDynamicSharedMemorySize, GSMEM);

    // 1. splits for in-proj
    split_hl<<<(ML * DMODEL / 4 + 255) / 256, 256>>>(x, p_xh, p_xl, ML * DMODEL / 4);
    split_hl<<<(2 * DIN * DMODEL / 4 + 255) / 256, 256>>>(W_in, p_Winh, p_Winl,
                                                          2 * DIN * DMODEL / 4);
    // 2. in-proj GEMM: (8192 x 4096) K=1024
    gemm_hl<0><<<dim3(4096 / 128, ML / 128), 256, GSMEM>>>(
        p_xh, p_xl, p_Winh, p_Winl, p_xz, 4096, DMODEL, nullptr);
    // 3. conv + SiLU (+ bf16 split of xc)
    conv_silu_kernel<<<(ML * DIN + 255) / 256, 256>>>(conv_w, conv_b);
    // 4. x-proj GEMM: (8192 x 96) K=2048
    split_hl<<<(DBCW * DIN / 4 + 255) / 256, 256>>>(W_x, p_Wxh, p_Wxl, DBCW * DIN / 4);
    gemm_hl<0><<<dim3(1, ML / 128), 256, GSMEM>>>(
        p_xch, p_xcl, p_Wxh, p_Wxl, p_dbc, DBCW, DIN, nullptr);
    // 5. delta GEMM with fused bias+softplus: (8192 x 2048) K=64
    split_dt_kernel<<<(ML * 16 + 255) / 256, 256>>>();
    split_hl<<<(DIN * DTRANK / 4 + 255) / 256, 256>>>(W_dt, p_Wdth, p_Wdtl,
                                                      DIN * DTRANK / 4);
    gemm_hl<1><<<dim3(DIN / 128, ML / 128), 256, GSMEM>>>(
        p_dth, p_dtl, p_Wdth, p_Wdtl, p_delta, DIN, DTRANK, b_dt);
    // 6. selective scan (+D skip, gate, bf16 split of y)
    scan_kernel<<<dim3(DIN / 64, BATCH), 256>>>(A_raw, Dp);
    // 7. out-proj GEMM: (8192 x 1024) K=2048
    split_hl<<<(DMODEL * DIN / 4 + 255) / 256, 256>>>(W_out, p_Wouth, p_Woutl,
                                                      DMODEL * DIN / 4);
    gemm_hl<0><<<dim3(DMODEL / 128, ML / 128), 256, GSMEM>>>(
        p_yh, p_yl, p_Wouth, p_Woutl, out, DMODEL, DIN, nullptr);
}